// round 14
// baseline (speedup 1.0000x reference)
#include <cuda_runtime.h>
#include <cuda_bf16.h>

// CrossNetwork (DCN-v1): x_{l+1} = input * (x_l . w_l) + x_l + b_l, L=6.
//
// Closed form: x_l = alpha_l*input + y_l,  y_l = sum_{j<l} b_j,
//   p_l = input.w_l, q_l = y_l.w_l,  alpha_{l+1} = alpha_l*(1+p_l)+q_l,
//   out = alpha_L*input + y_L.
//
// Round 14: 4 rows/warp quad processing. W smem reads amortized over 4 rows
// (12 crossbar-cyc/row vs 48 in the 2-row version). Input STREAMED through
// the dot loop (no retention -> ~75 regs -> 3 CTAs/SM), epilogue re-reads
// the quad's 16 KB from L2 (just touched). Warp-autonomous atomic stealing,
// zero mainloop barriers.

#define D 1024
#define L 6
#define NTHREADS 256
#define D4 (D / 4)          // 256 float4 per row
#define GRID_CTAS 444       // 148 SMs * 3 resident CTAs

__device__ unsigned int g_quad_ctr = 0;
__device__ unsigned int g_done_ctr = 0;

__global__ __launch_bounds__(NTHREADS, 3)
void crossnet_kernel(const float* __restrict__ input,
                     const float* __restrict__ Wg,
                     const float* __restrict__ bg,
                     float* __restrict__ out,
                     int B, int nquads, int totalwarps)
{
    __shared__ float4 w_s[L * D4];   // 24 KB: full W
    __shared__ float4 y_s[D4];       // 4 KB: y_L = sum_l b_l
    __shared__ float  q_s[L];        // 6 scalars

    const int tid  = threadIdx.x;
    const int lane = tid & 31;

    if (tid < L) q_s[tid] = 0.0f;

    // ---- one-time preamble: W -> smem ----
    const float4* W4 = reinterpret_cast<const float4*>(Wg);
    const float4* B4 = reinterpret_cast<const float4*>(bg);
#pragma unroll
    for (int i = 0; i < L; i++)
        w_s[i * D4 + tid] = W4[i * D4 + tid];
    __syncthreads();

    // ---- one-time: y_L and q_l (redundant per CTA; cheap) ----
    {
        float4 y = make_float4(0.f, 0.f, 0.f, 0.f);
        float ql[L];
#pragma unroll
        for (int l = 0; l < L; l++) {
            float4 w  = w_s[l * D4 + tid];
            float4 bb = B4[l * D4 + tid];
            ql[l] = y.x * w.x + y.y * w.y + y.z * w.z + y.w * w.w;
            y.x += bb.x; y.y += bb.y; y.z += bb.z; y.w += bb.w;
        }
        y_s[tid] = y;
#pragma unroll
        for (int l = 0; l < L; l++) {
            float v = ql[l];
#pragma unroll
            for (int o = 16; o > 0; o >>= 1)
                v += __shfl_xor_sync(0xffffffffu, v, o);
            if (lane == 0) atomicAdd(&q_s[l], v);
        }
    }
    __syncthreads();   // w_s, y_s, q_s final; NO barriers after this point

    const float4* inp  = reinterpret_cast<const float4*>(input);
    float4*       outp = reinterpret_cast<float4*>(out);

    // ---- warp-autonomous mainloop: pop quads (4 rows) ----
    for (;;) {
        unsigned int v = 0;
        if (lane == 0) v = atomicAdd(&g_quad_ctr, 1u);
        v = __shfl_sync(0xffffffffu, v, 0);
        if (v >= (unsigned int)nquads) break;

        const int row0 = 4 * (int)v;
        // clamp row indices for safe loads; stores guarded
        const int r0 = row0;
        const int r1 = (row0 + 1 < B) ? row0 + 1 : row0;
        const int r2 = (row0 + 2 < B) ? row0 + 2 : row0;
        const int r3 = (row0 + 3 < B) ? row0 + 3 : row0;

        const float4* p0 = inp + (size_t)r0 * D4;
        const float4* p1 = inp + (size_t)r1 * D4;
        const float4* p2 = inp + (size_t)r2 * D4;
        const float4* p3 = inp + (size_t)r3 * D4;

        float accA[L], accB[L], accC[L], accD[L];
#pragma unroll
        for (int l = 0; l < L; l++) {
            accA[l] = 0.f; accB[l] = 0.f; accC[l] = 0.f; accD[l] = 0.f;
        }

        // streamed dot: 4 LDG.128 + 6 LDS.128 + 96 FMA per k-chunk
#pragma unroll
        for (int k = 0; k < 8; k++) {
            const int idx = lane + 32 * k;
            float4 a = p0[idx];
            float4 b = p1[idx];
            float4 c = p2[idx];
            float4 d = p3[idx];
#pragma unroll
            for (int l = 0; l < L; l++) {
                float4 w = w_s[l * D4 + idx];
                accA[l] = fmaf(a.x, w.x, accA[l]);
                accA[l] = fmaf(a.y, w.y, accA[l]);
                accA[l] = fmaf(a.z, w.z, accA[l]);
                accA[l] = fmaf(a.w, w.w, accA[l]);
                accB[l] = fmaf(b.x, w.x, accB[l]);
                accB[l] = fmaf(b.y, w.y, accB[l]);
                accB[l] = fmaf(b.z, w.z, accB[l]);
                accB[l] = fmaf(b.w, w.w, accB[l]);
                accC[l] = fmaf(c.x, w.x, accC[l]);
                accC[l] = fmaf(c.y, w.y, accC[l]);
                accC[l] = fmaf(c.z, w.z, accC[l]);
                accC[l] = fmaf(c.w, w.w, accC[l]);
                accD[l] = fmaf(d.x, w.x, accD[l]);
                accD[l] = fmaf(d.y, w.y, accD[l]);
                accD[l] = fmaf(d.z, w.z, accD[l]);
                accD[l] = fmaf(d.w, w.w, accD[l]);
            }
        }

        // butterfly warp reductions (24 independent chains)
#pragma unroll
        for (int l = 0; l < L; l++) {
#pragma unroll
            for (int o = 16; o > 0; o >>= 1) {
                accA[l] += __shfl_xor_sync(0xffffffffu, accA[l], o);
                accB[l] += __shfl_xor_sync(0xffffffffu, accB[l], o);
                accC[l] += __shfl_xor_sync(0xffffffffu, accC[l], o);
                accD[l] += __shfl_xor_sync(0xffffffffu, accD[l], o);
            }
        }

        // scalar recurrence: alpha = alpha*(1+p) + q
        float aA = 1.0f, aB = 1.0f, aC = 1.0f, aD = 1.0f;
#pragma unroll
        for (int l = 0; l < L; l++) {
            float q = q_s[l];
            aA = fmaf(aA, accA[l], aA) + q;
            aB = fmaf(aB, accB[l], aB) + q;
            aC = fmaf(aC, accC[l], aC) + q;
            aD = fmaf(aD, accD[l], aD) + q;
        }

        // epilogue: re-read input (L2-hot), out = alpha*input + y_L
        float4* o0 = outp + (size_t)r0 * D4;
        float4* o1 = outp + (size_t)r1 * D4;
        float4* o2 = outp + (size_t)r2 * D4;
        float4* o3 = outp + (size_t)r3 * D4;
        const bool s1 = (row0 + 1 < B);
        const bool s2 = (row0 + 2 < B);
        const bool s3 = (row0 + 3 < B);
#pragma unroll
        for (int k = 0; k < 8; k++) {
            const int idx = lane + 32 * k;
            float4 y = y_s[idx];
            {
                float4 i0 = p0[idx];
                float4 r;
                r.x = fmaf(aA, i0.x, y.x);
                r.y = fmaf(aA, i0.y, y.y);
                r.z = fmaf(aA, i0.z, y.z);
                r.w = fmaf(aA, i0.w, y.w);
                o0[idx] = r;
            }
            if (s1) {
                float4 i1 = p1[idx];
                float4 r;
                r.x = fmaf(aB, i1.x, y.x);
                r.y = fmaf(aB, i1.y, y.y);
                r.z = fmaf(aB, i1.z, y.z);
                r.w = fmaf(aB, i1.w, y.w);
                o1[idx] = r;
            }
            if (s2) {
                float4 i2 = p2[idx];
                float4 r;
                r.x = fmaf(aC, i2.x, y.x);
                r.y = fmaf(aC, i2.y, y.y);
                r.z = fmaf(aC, i2.z, y.z);
                r.w = fmaf(aC, i2.w, y.w);
                o2[idx] = r;
            }
            if (s3) {
                float4 i3 = p3[idx];
                float4 r;
                r.x = fmaf(aD, i3.x, y.x);
                r.y = fmaf(aD, i3.y, y.y);
                r.z = fmaf(aD, i3.z, y.z);
                r.w = fmaf(aD, i3.w, y.w);
                o3[idx] = r;
            }
        }
    }

    // ---- reset counters for next graph replay (last warp out) ----
    if (lane == 0) {
        __threadfence();
        unsigned int d = atomicAdd(&g_done_ctr, 1u);
        if (d == (unsigned int)totalwarps - 1u) {
            atomicExch(&g_quad_ctr, 0u);
            atomicExch(&g_done_ctr, 0u);
        }
    }
}

extern "C" void kernel_launch(void* const* d_in, const int* in_sizes, int n_in,
                              void* d_out, int out_size)
{
    const float* input = (const float*)d_in[0];
    const float* W     = (const float*)d_in[1];
    const float* b     = (const float*)d_in[2];
    float* out         = (float*)d_out;

    const int B      = in_sizes[0] / D;          // 16384
    const int nquads = (B + 3) / 4;              // 4096
    int grid         = GRID_CTAS;                // 444
    const int maxg   = (nquads + (NTHREADS / 32) - 1) / (NTHREADS / 32);
    if (grid > maxg) grid = maxg;
    const int totalwarps = grid * (NTHREADS / 32);

    crossnet_kernel<<<grid, NTHREADS>>>(input, W, b, out, B, nquads, totalwarps);
}

// round 16
// speedup vs baseline: 2.0010x; 2.0010x over previous
#include <cuda_runtime.h>
#include <cuda_bf16.h>

// CrossNetwork (DCN-v1): x_{l+1} = input * (x_l . w_l) + x_l + b_l, L=6.
//
// Closed form: x_l = alpha_l*input + y_l,  y_l = sum_{j<l} b_j,
//   p_l = input.w_l, q_l = y_l.w_l,  alpha_{l+1} = alpha_l*(1+p_l)+q_l,
//   out = alpha_L*input + y_L.
// One HBM read + one HBM write of [B,D] (128 MB logical).
//
// Round 16: R15 cp.async double-buffered per-warp pair staging, with the
// stage-indexing bug fixed (row 1 lives at float4 offset 256 within the
// 8192-byte stage, not 512 -- 512 walked into the next stage and off the
// end of the allocation for warp 11).

#define D 1024
#define L 6
#define NTHREADS 384
#define NWARPS (NTHREADS / 32)       // 12
#define D4 (D / 4)                   // 256 float4 per row
#define GRID_CTAS 148                // 1 CTA/SM (smem-limited)

// dynamic smem layout (bytes)
#define SM_W    0                          // 1536 float4 = 24576
#define SM_Y    (SM_W + L * D4 * 16)       // 256 float4  = 4096
#define SM_Q    (SM_Y + D4 * 16)           // 6 floats (pad 32)
#define SM_BUF  (SM_Q + 32)                // 12 warps * 2 stages * 8192 B
#define SM_TOTAL (SM_BUF + NWARPS * 2 * 8192)   // 225312

__device__ unsigned int g_pair_ctr = 0;
__device__ unsigned int g_done_ctr = 0;

__device__ __forceinline__ void cp_async16(unsigned int smem_addr, const void* gptr) {
    asm volatile("cp.async.cg.shared.global [%0], [%1], 16;"
                 :: "r"(smem_addr), "l"(gptr));
}
__device__ __forceinline__ void cp_commit() {
    asm volatile("cp.async.commit_group;" ::: "memory");
}
__device__ __forceinline__ void cp_wait1() {
    asm volatile("cp.async.wait_group 1;" ::: "memory");
}

__global__ __launch_bounds__(NTHREADS, 1)
void crossnet_kernel(const float* __restrict__ input,
                     const float* __restrict__ Wg,
                     const float* __restrict__ bg,
                     float* __restrict__ out,
                     int B, int npairs, int totalwarps)
{
    extern __shared__ char smem[];
    float4* w_s = reinterpret_cast<float4*>(smem + SM_W);
    float4* y_s = reinterpret_cast<float4*>(smem + SM_Y);
    float*  q_s = reinterpret_cast<float*>(smem + SM_Q);

    const int tid  = threadIdx.x;
    const int lane = tid & 31;
    const int warp = tid >> 5;

    if (tid < L) q_s[tid] = 0.0f;

    // ---- one-time preamble: W -> smem ----
    const float4* W4 = reinterpret_cast<const float4*>(Wg);
    const float4* B4 = reinterpret_cast<const float4*>(bg);
    for (int i = tid; i < L * D4; i += NTHREADS)
        w_s[i] = W4[i];
    __syncthreads();

    // ---- one-time: y_L and q_l (first 256 threads own one column group) ----
    if (tid < D4) {
        float4 y = make_float4(0.f, 0.f, 0.f, 0.f);
        float ql[L];
#pragma unroll
        for (int l = 0; l < L; l++) {
            float4 w  = w_s[l * D4 + tid];
            float4 bb = B4[l * D4 + tid];
            ql[l] = y.x * w.x + y.y * w.y + y.z * w.z + y.w * w.w;
            y.x += bb.x; y.y += bb.y; y.z += bb.z; y.w += bb.w;
        }
        y_s[tid] = y;
#pragma unroll
        for (int l = 0; l < L; l++) {
            float v = ql[l];
#pragma unroll
            for (int o = 16; o > 0; o >>= 1)
                v += __shfl_xor_sync(0xffffffffu, v, o);
            if (lane == 0) atomicAdd(&q_s[l], v);
        }
    }
    __syncthreads();   // w_s, y_s, q_s final; NO barriers after this point

    const float4* inp  = reinterpret_cast<const float4*>(input);
    float4*       outp = reinterpret_cast<float4*>(out);

    // per-warp stage buffers: stage s at buf_base + s*8192
    unsigned int buf_base = (unsigned int)__cvta_generic_to_shared(smem + SM_BUF)
                          + (unsigned int)warp * 2u * 8192u;

#define POP(dst)                                                           \
    {                                                                      \
        unsigned int t_ = 0;                                               \
        if (lane == 0) t_ = atomicAdd(&g_pair_ctr, 1u);                    \
        dst = __shfl_sync(0xffffffffu, t_, 0);                             \
    }

    // issue 16 cp.async (2 rows x 8 chunks) for pair v into stage s.
    // stage layout: row0 at float4 [0,256), row1 at float4 [256,512)
#define ISSUE(v, s)                                                        \
    {                                                                      \
        const int r0_ = 2 * (int)(v);                                      \
        const int r1_ = (r0_ + 1 < B) ? r0_ + 1 : r0_;                     \
        const float4* g0_ = inp + (size_t)r0_ * D4;                        \
        const float4* g1_ = inp + (size_t)r1_ * D4;                        \
        unsigned int sb_ = buf_base + (unsigned int)(s) * 8192u;           \
        _Pragma("unroll")                                                  \
        for (int k = 0; k < 8; k++) {                                      \
            const int idx_ = lane + 32 * k;                                \
            cp_async16(sb_ + idx_ * 16u,         g0_ + idx_);              \
            cp_async16(sb_ + (256 + idx_) * 16u, g1_ + idx_);              \
        }                                                                  \
    }

    unsigned int cur, nxt;
    POP(cur);
    if (cur < (unsigned int)npairs) ISSUE(cur, 0);
    cp_commit();
    POP(nxt);
    if (nxt < (unsigned int)npairs) ISSUE(nxt, 1);
    cp_commit();

    int s = 0;
    while (cur < (unsigned int)npairs) {
        cp_wait1();   // stage s ready (all but newest group drained)

        const float4* sbuf = reinterpret_cast<const float4*>(
            smem + SM_BUF + (size_t)warp * 2 * 8192 + (size_t)s * 8192);

        // lift input smem -> regs (one LDS pass), compute dot
        float4 in0[8], in1[8];
        float acc0[L], acc1[L];
#pragma unroll
        for (int l = 0; l < L; l++) { acc0[l] = 0.f; acc1[l] = 0.f; }

#pragma unroll
        for (int k = 0; k < 8; k++) {
            const int idx = lane + 32 * k;
            in0[k] = sbuf[idx];
            in1[k] = sbuf[256 + idx];
#pragma unroll
            for (int l = 0; l < L; l++) {
                float4 w = w_s[l * D4 + idx];
                acc0[l] = fmaf(in0[k].x, w.x, acc0[l]);
                acc0[l] = fmaf(in0[k].y, w.y, acc0[l]);
                acc0[l] = fmaf(in0[k].z, w.z, acc0[l]);
                acc0[l] = fmaf(in0[k].w, w.w, acc0[l]);
                acc1[l] = fmaf(in1[k].x, w.x, acc1[l]);
                acc1[l] = fmaf(in1[k].y, w.y, acc1[l]);
                acc1[l] = fmaf(in1[k].z, w.z, acc1[l]);
                acc1[l] = fmaf(in1[k].w, w.w, acc1[l]);
            }
        }

        // refill this stage with the pair after next, ASAP (keeps loads live)
        unsigned int vnew;
        POP(vnew);
        if (vnew < (unsigned int)npairs) ISSUE(vnew, s);
        cp_commit();

        // butterfly warp reductions -> every lane holds full p_l
#pragma unroll
        for (int l = 0; l < L; l++) {
#pragma unroll
            for (int o = 16; o > 0; o >>= 1) {
                acc0[l] += __shfl_xor_sync(0xffffffffu, acc0[l], o);
                acc1[l] += __shfl_xor_sync(0xffffffffu, acc1[l], o);
            }
        }

        // scalar recurrence: alpha = alpha*(1+p) + q
        float a0 = 1.0f, a1 = 1.0f;
#pragma unroll
        for (int l = 0; l < L; l++) {
            float q = q_s[l];
            a0 = fmaf(a0, acc0[l], a0) + q;
            a1 = fmaf(a1, acc1[l], a1) + q;
        }

        // epilogue: out = alpha * input + y_L (input from registers)
        const int row0 = 2 * (int)cur;
        const bool s1ok = (row0 + 1 < B);
        float4* o0 = outp + (size_t)row0 * D4;
        float4* o1 = o0 + D4;
#pragma unroll
        for (int k = 0; k < 8; k++) {
            const int idx = lane + 32 * k;
            float4 y = y_s[idx];
            float4 r0;
            r0.x = fmaf(a0, in0[k].x, y.x);
            r0.y = fmaf(a0, in0[k].y, y.y);
            r0.z = fmaf(a0, in0[k].z, y.z);
            r0.w = fmaf(a0, in0[k].w, y.w);
            o0[idx] = r0;
            if (s1ok) {
                float4 r1;
                r1.x = fmaf(a1, in1[k].x, y.x);
                r1.y = fmaf(a1, in1[k].y, y.y);
                r1.z = fmaf(a1, in1[k].z, y.z);
                r1.w = fmaf(a1, in1[k].w, y.w);
                o1[idx] = r1;
            }
        }

        s ^= 1;
        cur = nxt;
        nxt = vnew;
    }
#undef POP
#undef ISSUE

    // ---- reset counters for next graph replay (last warp out) ----
    if (lane == 0) {
        __threadfence();
        unsigned int d = atomicAdd(&g_done_ctr, 1u);
        if (d == (unsigned int)totalwarps - 1u) {
            atomicExch(&g_pair_ctr, 0u);
            atomicExch(&g_done_ctr, 0u);
        }
    }
}

extern "C" void kernel_launch(void* const* d_in, const int* in_sizes, int n_in,
                              void* d_out, int out_size)
{
    const float* input = (const float*)d_in[0];
    const float* W     = (const float*)d_in[1];
    const float* b     = (const float*)d_in[2];
    float* out         = (float*)d_out;

    const int B      = in_sizes[0] / D;          // 16384
    const int npairs = (B + 1) / 2;              // 8192
    int grid         = GRID_CTAS;                // 148
    const int maxg   = (npairs + NWARPS - 1) / NWARPS;
    if (grid > maxg) grid = maxg;
    const int totalwarps = grid * NWARPS;

    cudaFuncSetAttribute(crossnet_kernel,
                         cudaFuncAttributeMaxDynamicSharedMemorySize, SM_TOTAL);
    crossnet_kernel<<<grid, NTHREADS, SM_TOTAL>>>(input, W, b, out,
                                                  B, npairs, totalwarps);
}